// round 7
// baseline (speedup 1.0000x reference)
#include <cuda_runtime.h>

// Effective weights: w_eff_m[u] = sum_v W_lin_m[u,v] * W_tp_m[v], pre-scaled.
// s0 = lin_norm*alpha = 1/(16*sqrt(768)); s1 = s0/sqrt(3); s2 = s0/sqrt(5)
__device__ float g_w[3 * 256];

#define S0 0.0022552744890219763f
#define S1 0.0013020833333333333f
#define S2 0.0010085837883053976f

// One warp per output row u (768 rows): 96 blocks x 8 warps. Also zeroes the
// output buffer (fused so the energy kernel has a single upstream dependency
// and we skip a separate memset node).
__global__ void __launch_bounds__(256)
prep_weights_kernel(const float* __restrict__ W0,
                    const float* __restrict__ W1,
                    const float* __restrict__ W2,
                    const float* __restrict__ T0,
                    const float* __restrict__ T1,
                    const float* __restrict__ T2,
                    float* __restrict__ out, int n) {
    // Zero the output (strided across all 24576 threads).
    int gt = blockIdx.x * 256 + threadIdx.x;
    for (int i = gt; i < n; i += 96 * 256) out[i] = 0.f;

    int gw = blockIdx.x * 8 + (threadIdx.x >> 5);   // u index 0..767
    int lane = threadIdx.x & 31;
    int m = gw >> 8;
    int u = gw & 255;

    const float* W = (m == 0) ? W0 : (m == 1) ? W1 : W2;
    const float* T = (m == 0) ? T0 : (m == 1) ? T1 : T2;
    float scale = (m == 0) ? S0 : (m == 1) ? S1 : S2;

    const float4* row4 = (const float4*)(W + (size_t)u * 256) + lane * 2;
    const float4* t4   = (const float4*)T + lane * 2;

    float4 r0 = row4[0], r1 = row4[1];
    float4 w0 = t4[0],   w1 = t4[1];

    float acc = r0.x * w0.x + r0.y * w0.y + r0.z * w0.z + r0.w * w0.w
              + r1.x * w1.x + r1.y * w1.y + r1.z * w1.z + r1.w * w1.w;
#pragma unroll
    for (int off = 16; off; off >>= 1)
        acc += __shfl_xor_sync(0xffffffffu, acc, off);
    if (lane == 0) g_w[m * 256 + u] = acc * scale;
}

// One balanced wave: grid = 592 = 148 SMs x 3+ CTAs. Each block owns a
// contiguous node range (<=128 nodes). Charges staged in SMEM once (single
// barrier). Main loop is barrier-free and SOFTWARE-PIPELINED: node i+1's
// coalesced float4 streaming loads are issued before node i's FMA/shuffle/
// atomic tail, so the reduce tail overlaps the next DRAM latency. Double
// buffer, manual unroll-by-2 (no register copies).
__global__ void __launch_bounds__(256, 3)
energy_kernel(const float* __restrict__ nf,
              const float* __restrict__ ch,
              float* __restrict__ out, int n, int nblk) {
    __shared__ float cbuf[128 * 9];

    long base = (long)blockIdx.x * n / nblk;
    long end  = (long)(blockIdx.x + 1) * n / nblk;
    int cnt = (int)(end - base);
    if (cnt <= 0) return;

    int t = threadIdx.x;
    int lane = t & 31;

    // Per-thread element metadata (fixed):
    // slot A: float4 q = t        -> j = 4t+e            (x0 if t<64 else x1)
    // slot B: float4 q = t + 256  -> j = 1024 + 4t + e   (x2)
    // slot C: float4 q = t + 512  -> j = 2048 + 4t + e   (x2, t<64 only)
    float aA[4], aB[4], aC[4];
    int kA[4], kB[4], kC[4];
#pragma unroll
    for (int e = 0; e < 4; e++) {
        int jA = 4 * t + e;
        if (jA < 256) { aA[e] = g_w[jA]; kA[e] = 0; }
        else { int r = jA - 256; aA[e] = g_w[256 + r / 3]; kA[e] = 1 + r % 3; }
        int rB = 4 * t + e;
        aB[e] = g_w[512 + rB / 5]; kB[e] = 4 + rB % 5;
        int rC = 1024 + 4 * t + e;
        if (t < 64) { aC[e] = g_w[512 + rC / 5]; kC[e] = 4 + rC % 5; }
        else        { aC[e] = 0.f; kC[e] = 0; }
    }

    // Stage this block's charges once.
    {
        int total = cnt * 9;
        const float* cp = ch + base * 9;
        for (int i = t; i < total; i += 256) cbuf[i] = __ldg(cp + i);
    }
    __syncthreads();

    const float4* base4 = (const float4*)(nf + base * 2304);
    bool low = (t < 64);

    auto LOAD = [&](float4& A, float4& B, float4& C, int i) {
        const float4* p = base4 + (size_t)i * 576;
        A = __ldcs(p + t);
        B = __ldcs(p + 256 + t);
        if (low) C = __ldcs(p + 512 + t);
    };

    auto COMP = [&](float4& A, float4& B, float4& C, int i) {
        const float* cb = cbuf + 9 * i;
        float acc;
        if (low) {
            acc = cb[0] * (A.x * aA[0] + A.y * aA[1] + A.z * aA[2] + A.w * aA[3]);
#pragma unroll
            for (int e = 0; e < 4; e++)
                acc = fmaf((&C.x)[e], aC[e] * cb[kC[e]], acc);
        } else {
            acc = 0.f;
#pragma unroll
            for (int e = 0; e < 4; e++)
                acc = fmaf((&A.x)[e], aA[e] * cb[kA[e]], acc);
        }
#pragma unroll
        for (int e = 0; e < 4; e++)
            acc = fmaf((&B.x)[e], aB[e] * cb[kB[e]], acc);
#pragma unroll
        for (int off = 16; off; off >>= 1)
            acc += __shfl_xor_sync(0xffffffffu, acc, off);
        if (lane == 0) atomicAdd(&out[base + i], acc);
    };

    float4 Z = make_float4(0.f, 0.f, 0.f, 0.f);
    float4 A0 = Z, B0 = Z, C0 = Z, A1 = Z, B1 = Z, C1 = Z;

    LOAD(A0, B0, C0, 0);
    int loc = 0;
    while (true) {
        if (loc + 1 < cnt) LOAD(A1, B1, C1, loc + 1);
        COMP(A0, B0, C0, loc);
        if (++loc >= cnt) break;
        if (loc + 1 < cnt) LOAD(A0, B0, C0, loc + 1);
        COMP(A1, B1, C1, loc);
        if (++loc >= cnt) break;
    }
}

extern "C" void kernel_launch(void* const* d_in, const int* in_sizes, int n_in,
                              void* d_out, int out_size) {
    const float* node_feats = (const float*)d_in[0];
    const float* charges    = (const float*)d_in[1];
    const float* W_lin0     = (const float*)d_in[2];
    const float* W_lin1     = (const float*)d_in[3];
    const float* W_lin2     = (const float*)d_in[4];
    const float* W_tp0      = (const float*)d_in[5];
    const float* W_tp1      = (const float*)d_in[6];
    const float* W_tp2      = (const float*)d_in[7];
    float* out = (float*)d_out;

    int n = in_sizes[1] / 9;   // number of nodes

    prep_weights_kernel<<<96, 256>>>(W_lin0, W_lin1, W_lin2,
                                     W_tp0, W_tp1, W_tp2, out, n);

    // One balanced wave. Guarantee <=128 nodes/block (cbuf capacity).
    int nblk = 592;
    int minblk = (n + 127) / 128;
    if (minblk > nblk) nblk = minblk;
    energy_kernel<<<nblk, 256>>>(node_feats, charges, out, n, nblk);
}

// round 8
// speedup vs baseline: 1.3806x; 1.3806x over previous
#include <cuda_runtime.h>

// Effective weights: w_eff_m[u] = sum_v W_lin_m[u,v] * W_tp_m[v], pre-scaled.
// s0 = lin_norm*alpha = 1/(16*sqrt(768)); s1 = s0/sqrt(3); s2 = s0/sqrt(5)
__device__ float g_w[3 * 256];

#define S0 0.0022552744890219763f
#define S1 0.0013020833333333333f
#define S2 0.0010085837883053976f

// One warp per output row u (768 rows): 96 blocks x 8 warps. Also zeroes the
// output buffer (fused: no separate memset node in the graph).
__global__ void __launch_bounds__(256)
prep_weights_kernel(const float* __restrict__ W0,
                    const float* __restrict__ W1,
                    const float* __restrict__ W2,
                    const float* __restrict__ T0,
                    const float* __restrict__ T1,
                    const float* __restrict__ T2,
                    float* __restrict__ out, int n) {
    int gt = blockIdx.x * 256 + threadIdx.x;
    for (int i = gt; i < n; i += 96 * 256) out[i] = 0.f;

    int gw = blockIdx.x * 8 + (threadIdx.x >> 5);   // u index 0..767
    int lane = threadIdx.x & 31;
    int m = gw >> 8;
    int u = gw & 255;

    const float* W = (m == 0) ? W0 : (m == 1) ? W1 : W2;
    const float* T = (m == 0) ? T0 : (m == 1) ? T1 : T2;
    float scale = (m == 0) ? S0 : (m == 1) ? S1 : S2;

    const float4* row4 = (const float4*)(W + (size_t)u * 256) + lane * 2;
    const float4* t4   = (const float4*)T + lane * 2;

    float4 r0 = row4[0], r1 = row4[1];
    float4 w0 = t4[0],   w1 = t4[1];

    float acc = r0.x * w0.x + r0.y * w0.y + r0.z * w0.z + r0.w * w0.w
              + r1.x * w1.x + r1.y * w1.y + r1.z * w1.z + r1.w * w1.w;
#pragma unroll
    for (int off = 16; off; off >>= 1)
        acc += __shfl_xor_sync(0xffffffffu, acc, off);
    if (lane == 0) g_w[m * 256 + u] = acc * scale;
}

// R5 main kernel (measured 92.7us @ 83% DRAM, regs=64, 4 CTAs/SM).
// One balanced wave: grid = 592 = 148 SMs x 4 CTAs. Each block owns a
// contiguous node range (<=128 nodes). Charges staged in SMEM once (single
// barrier). Main loop is barrier-free: 2 nodes/iter, front-batched float4
// streaming loads, per-element weight(reg) x charge(SMEM select) FMAs,
// interleaved warp shuffle reduce, one atomicAdd per warp per node into the
// pre-zeroed output.
__global__ void __launch_bounds__(256, 4)
energy_kernel(const float* __restrict__ nf,
              const float* __restrict__ ch,
              float* __restrict__ out, int n, int nblk) {
    __shared__ float cbuf[128 * 9];

    long base = (long)blockIdx.x * n / nblk;
    long end  = (long)(blockIdx.x + 1) * n / nblk;
    int cnt = (int)(end - base);
    if (cnt <= 0) return;

    int t = threadIdx.x;
    int lane = t & 31;

    // Per-thread element metadata (fixed):
    // slot A: float4 q = t        -> j = 4t+e            (x0 if t<64 else x1)
    // slot B: float4 q = t + 256  -> j = 1024 + 4t + e   (x2)
    // slot C: float4 q = t + 512  -> j = 2048 + 4t + e   (x2, t<64 only)
    float aA[4], aB[4], aC[4];
    int kA[4], kB[4], kC[4];
#pragma unroll
    for (int e = 0; e < 4; e++) {
        int jA = 4 * t + e;
        if (jA < 256) { aA[e] = g_w[jA]; kA[e] = 0; }
        else { int r = jA - 256; aA[e] = g_w[256 + r / 3]; kA[e] = 1 + r % 3; }
        int rB = 4 * t + e;
        aB[e] = g_w[512 + rB / 5]; kB[e] = 4 + rB % 5;
        int rC = 1024 + 4 * t + e;
        if (t < 64) { aC[e] = g_w[512 + rC / 5]; kC[e] = 4 + rC % 5; }
        else        { aC[e] = 0.f; kC[e] = 0; }
    }

    // Stage this block's charges once.
    {
        int total = cnt * 9;
        const float* cp = ch + base * 9;
        for (int i = t; i < total; i += 256) cbuf[i] = __ldg(cp + i);
    }
    __syncthreads();

    for (int loc = 0; loc < cnt; loc += 2) {
        long z0 = base + loc;
        bool v1 = (loc + 1) < cnt;

        const float4* p0 = (const float4*)(nf + z0 * 2304);
        const float4* p1 = p0 + 576;

        float4 Z = make_float4(0.f, 0.f, 0.f, 0.f);
        float4 A0 = __ldcs(p0 + t), B0 = __ldcs(p0 + 256 + t);
        float4 C0 = Z, A1 = Z, B1 = Z, C1 = Z;
        if (t < 64) C0 = __ldcs(p0 + 512 + t);
        if (v1) {
            A1 = __ldcs(p1 + t); B1 = __ldcs(p1 + 256 + t);
            if (t < 64) C1 = __ldcs(p1 + 512 + t);
        }

        const float* cb0 = cbuf + 9 * loc;
        const float* cb1 = cb0 + 9;

        float acc0, acc1;
        if (t < 64) {
            acc0 = cb0[0] * (A0.x * aA[0] + A0.y * aA[1] + A0.z * aA[2] + A0.w * aA[3]);
            acc1 = cb1[0] * (A1.x * aA[0] + A1.y * aA[1] + A1.z * aA[2] + A1.w * aA[3]);
#pragma unroll
            for (int e = 0; e < 4; e++) {
                acc0 = fmaf((&C0.x)[e], aC[e] * cb0[kC[e]], acc0);
                acc1 = fmaf((&C1.x)[e], aC[e] * cb1[kC[e]], acc1);
            }
        } else {
            acc0 = 0.f; acc1 = 0.f;
#pragma unroll
            for (int e = 0; e < 4; e++) {
                acc0 = fmaf((&A0.x)[e], aA[e] * cb0[kA[e]], acc0);
                acc1 = fmaf((&A1.x)[e], aA[e] * cb1[kA[e]], acc1);
            }
        }
#pragma unroll
        for (int e = 0; e < 4; e++) {
            acc0 = fmaf((&B0.x)[e], aB[e] * cb0[kB[e]], acc0);
            acc1 = fmaf((&B1.x)[e], aB[e] * cb1[kB[e]], acc1);
        }

        // Interleaved warp reductions (two independent chains).
#pragma unroll
        for (int off = 16; off; off >>= 1) {
            acc0 += __shfl_xor_sync(0xffffffffu, acc0, off);
            acc1 += __shfl_xor_sync(0xffffffffu, acc1, off);
        }

        if (lane == 0) {
            atomicAdd(&out[z0], acc0);
            if (v1) atomicAdd(&out[z0 + 1], acc1);
        }
    }
}

extern "C" void kernel_launch(void* const* d_in, const int* in_sizes, int n_in,
                              void* d_out, int out_size) {
    const float* node_feats = (const float*)d_in[0];
    const float* charges    = (const float*)d_in[1];
    const float* W_lin0     = (const float*)d_in[2];
    const float* W_lin1     = (const float*)d_in[3];
    const float* W_lin2     = (const float*)d_in[4];
    const float* W_tp0      = (const float*)d_in[5];
    const float* W_tp1      = (const float*)d_in[6];
    const float* W_tp2      = (const float*)d_in[7];
    float* out = (float*)d_out;

    int n = in_sizes[1] / 9;   // number of nodes

    prep_weights_kernel<<<96, 256>>>(W_lin0, W_lin1, W_lin2,
                                     W_tp0, W_tp1, W_tp2, out, n);

    // One balanced wave: 148 SMs x 4 CTAs/SM. Guarantee <=128 nodes/block.
    int nblk = 592;
    int minblk = (n + 127) / 128;
    if (minblk > nblk) nblk = minblk;
    energy_kernel<<<nblk, 256>>>(node_feats, charges, out, n, nblk);
}